// round 10
// baseline (speedup 1.0000x reference)
#include <cuda_runtime.h>
#include <cuda_fp16.h>
#include <cstdint>

#define L_FFT   1024
#define NBINS   513
#define NBATCH  16
#define NCH     8
#define NT      250
#define NPAIRS  28
#define NLAGS   64

#define GT      5                 // t-units per GEMM CTA
#define NTBLK   (NT / GT)         // 50
#define MROWS   (GT * NPAIRS)     // 140
#define MPAD    144               // 9 m16 tiles
#define KKDIM   1026              // 513 bins x (Re,Im)
#define KKPAD   1040              // 65 x 16
#define NCHUNK  (KKPAD / 16)      // 65
#define APITCH  24                // halves per A smem row (48B)
#define BPITCH  72                // halves per B smem row (144B)

typedef unsigned long long ull;

// Scratch: PHASE-NORMALIZED spectra (unit magnitude) in fp16 complex. ~66 MB.
__device__ __half2 g_X[(size_t)NBATCH * NCH * NT * NBINS];
// Constant DFT matrix B[kk][j], fp16, row-major 64 cols. Filled per launch.
__device__ __half g_B[(size_t)KKPAD * NLAGS];

__constant__ int c_i1[NPAIRS] = {0,0,0,0,0,0,0,1,1,1,1,1,1,2,2,2,2,2,3,3,3,3,4,4,4,5,5,6};
__constant__ int c_i2[NPAIRS] = {1,2,3,4,5,6,7,2,3,4,5,6,7,3,4,5,6,7,4,5,6,7,5,6,7,6,7,7};

// Pass-2 twiddle LUT: e^{2 pi i j / 64}, j = 0..7
__constant__ float2 c_w64[8] = {
    {1.0f, 0.0f},
    {0.99518472667219689f, 0.09801714032956060f},
    {0.98078528040323045f, 0.19509032201612827f},
    {0.95694033573220887f, 0.29028467725446234f},
    {0.92387953251128676f, 0.38268343236508977f},
    {0.88192126434835503f, 0.47139673682599764f},
    {0.83146961230254524f, 0.55557023301960222f},
    {0.77301045336273696f, 0.63439328416364549f}
};

union C64u { float2 f; ull u; };
__device__ __forceinline__ ull   F2U(float2 a){ C64u c; c.f=a; return c.u; }
__device__ __forceinline__ float2 U2F(ull a){ C64u c; c.u=a; return c.f; }

__device__ __forceinline__ ull padd(ull a, ull b){ ull r; asm("add.rn.f32x2 %0,%1,%2;" : "=l"(r) : "l"(a), "l"(b)); return r; }
__device__ __forceinline__ ull psub(ull a, ull b){ ull r; asm("sub.rn.f32x2 %0,%1,%2;" : "=l"(r) : "l"(a), "l"(b)); return r; }
__device__ __forceinline__ ull pmulp(ull a, ull b){ ull r; asm("mul.rn.f32x2 %0,%1,%2;" : "=l"(r) : "l"(a), "l"(b)); return r; }

__device__ __forceinline__ float2 cadd(float2 a, float2 b){ return make_float2(a.x+b.x, a.y+b.y); }
__device__ __forceinline__ float2 cmul(float2 a, float2 b){ return make_float2(a.x*b.x - a.y*b.y, a.x*b.y + a.y*b.x); }

template<int S>
__device__ __forceinline__ ull muli(ull a){
    float2 f = U2F(a);
    return F2U(S > 0 ? make_float2(-f.y, f.x) : make_float2(f.y, -f.x));
}

#define PD(i) ((i) + ((i) >> 3))
#define ABUF  576

template<int S>
__device__ __forceinline__ void pbfly8(ull v[8]) {
    const float Cc = 0.70710678118654752440f;
    const ull CC = F2U(make_float2(Cc, Cc));
    ull t0 = padd(v[0], v[4]), t4 = psub(v[0], v[4]);
    ull t1 = padd(v[1], v[5]), t5 = psub(v[1], v[5]);
    ull t2 = padd(v[2], v[6]), t6 = psub(v[2], v[6]);
    ull t3 = padd(v[3], v[7]), t7 = psub(v[3], v[7]);
    ull u5 = pmulp(CC, padd(t5, muli<S>(t5)));
    ull u6 = muli<S>(t6);
    ull u7 = pmulp(CC, psub(muli<S>(t7), t7));
    ull p0 = padd(t0, t2), q0 = psub(t0, t2);
    ull p1 = padd(t1, t3), q1 = muli<S>(psub(t1, t3));
    v[0] = padd(p0, p1); v[4] = psub(p0, p1);
    v[2] = padd(q0, q1); v[6] = psub(q0, q1);
    ull r0 = padd(t4, u6), s0 = psub(t4, u6);
    ull r1 = padd(u5, u7), s1 = muli<S>(psub(u5, u7));
    v[1] = padd(r0, r1); v[5] = psub(r0, r1);
    v[3] = padd(s0, s1); v[7] = psub(s0, s1);
}

__device__ __forceinline__ void twiddle7(ull v[8], float2 w){
    float2 w2 = cmul(w,  w);
    float2 w3 = cmul(w2, w);
    float2 w4 = cmul(w2, w2);
    float2 w5 = cmul(w3, w2);
    float2 w6 = cmul(w3, w3);
    float2 w7 = cmul(w4, w3);
    v[1] = F2U(cmul(U2F(v[1]), w));
    v[2] = F2U(cmul(U2F(v[2]), w2));
    v[3] = F2U(cmul(U2F(v[3]), w3));
    v[4] = F2U(cmul(U2F(v[4]), w4));
    v[5] = F2U(cmul(U2F(v[5]), w5));
    v[6] = F2U(cmul(U2F(v[6]), w6));
    v[7] = F2U(cmul(U2F(v[7]), w7));
}

template<int S>
__device__ __forceinline__ void fft_mid(float2* A, ull v[8], int t){
    int n3 = t & 7;
    int b2 = 64 * (t >> 3) + n3;
    #pragma unroll
    for (int l = 0; l < 8; l++) v[l] = F2U(A[PD(b2 + 8*l)]);
    pbfly8<S>(v);
    {
        float2 w = c_w64[n3];
        twiddle7(v, S > 0 ? w : make_float2(w.x, -w.y));
    }
    #pragma unroll
    for (int l = 0; l < 8; l++) A[PD(b2 + 8*l)] = U2F(v[l]);
    __syncthreads();
    #pragma unroll
    for (int l = 0; l < 8; l++) v[l] = F2U(A[PD(8*t + l)]);
    pbfly8<S>(v);
}

// ---------------- Kernel A: forward rfft + PHAT phase-normalize ----------------
__global__ __launch_bounds__(64) void fwd_fft_kernel(const float* __restrict__ x) {
    __shared__ float2 A[ABUF];
    int t = threadIdx.x;
    int row = blockIdx.x;
    const float2* xin = reinterpret_cast<const float2*>(x + (size_t)row * L_FFT);

    float sT, cT; sincospif((float)t * (1.0f/512.0f), &sT, &cT);
    float2 Tt = make_float2(cT, sT);

    ull v[8];
    #pragma unroll
    for (int l = 0; l < 8; l++) v[l] = F2U(xin[t + 64*l]);
    pbfly8<-1>(v);
    {
        float2 T2 = cmul(Tt, Tt);
        twiddle7(v, make_float2(T2.x, -T2.y));
    }
    #pragma unroll
    for (int j = 0; j < 8; j++) A[PD(t + 64*j)] = U2F(v[j]);
    __syncthreads();

    fft_mid<-1>(A, v, t);
    __syncthreads();
    int base = (t >> 3) + 8 * (t & 7);
    #pragma unroll
    for (int m = 0; m < 8; m++) A[PD(base + 64*m)] = U2F(v[m]);
    __syncthreads();

    __half2* outp = g_X + (size_t)row * NBINS;
    const float2 W64t = make_float2(0.92387953251128676f, 0.38268343236508977f);
    float sB, cB; sincospif((float)base * (1.0f/512.0f), &sB, &cB);
    float2 Tk = make_float2(cB, sB);
    #pragma unroll
    for (int m = 0; m < 8; m++) {
        int k = base + 64*m;
        float2 Zk = U2F(v[m]);
        float2 Zm = A[PD((512 - k) & 511)];
        float2 Ze = make_float2(0.5f * (Zk.x + Zm.x), 0.5f * (Zk.y - Zm.y));
        float2 D  = make_float2(Zk.x - Zm.x, Zk.y + Zm.y);
        float2 Zo = make_float2(0.5f * D.y, -0.5f * D.x);
        float2 tw = make_float2(Tk.x, -Tk.y);
        float2 X  = cadd(Ze, cmul(tw, Zo));
        float inv = rsqrtf(fmaxf(X.x*X.x + X.y*X.y, 1e-30f));
        outp[k] = __floats2half2_rn(X.x * inv, X.y * inv);
        Tk = cmul(Tk, W64t);
    }
    if (t == 0) {
        float2 Z0 = U2F(v[0]);
        float Xr = Z0.x - Z0.y;
        float inv = rsqrtf(fmaxf(Xr*Xr, 1e-30f));
        outp[512] = __floats2half2_rn(Xr * inv, 0.0f);
    }
}

// ---------------- Kernel B0: fill the constant DFT matrix g_B ----------------
// B[2k][j]   =  w_k * cos(pi * k * (j-32) / 512)
// B[2k+1][j] = -w_k * sin(pi * k * (j-32) / 512),  w_k = 2/1024 (1/1024 at k=0,512)
__global__ __launch_bounds__(256) void binit_kernel() {
    int idx = blockIdx.x * 256 + threadIdx.x;
    if (idx >= KKPAD * NLAGS) return;
    int kk = idx >> 6;
    int j  = idx & 63;
    float val = 0.0f;
    if (kk < KKDIM) {
        int k = kk >> 1;
        int n = j - 32;
        float w = (k == 0 || k == 512) ? (1.0f/1024.0f) : (2.0f/1024.0f);
        float s, c;
        sincospif((float)(k * n) * (1.0f/512.0f), &s, &c);
        val = (kk & 1) ? (-w * s) : (w * c);
    }
    g_B[idx] = __float2half(val);
}

// ---------------- Kernel B: cross-phase + lag-DFT as HMMA GEMM ----------------
// One CTA per (b, block of GT=5 t's). out[MROWS=140, 64] = A[140, 1026] x B.
// A row rho = tl*28 + p holds interleaved (Re,Im) of R[p][k] at time t=tblk*5+tl.
__global__ __launch_bounds__(256) void xgemm_kernel(float* __restrict__ out) {
    __shared__ __half As[MPAD * APITCH];   // chunk: 144 x 16 halves (pitch 24)
    __shared__ __half Bs[16 * BPITCH];     // chunk: 16 x 64 halves (pitch 72)

    int tid  = threadIdx.x;
    int cta  = blockIdx.x;
    int tblk = cta % NTBLK;
    int b    = cta / NTBLK;
    int lane = tid & 31;
    int warp = tid >> 5;       // n-tile id, 0..7

    float acc[9][4];
    #pragma unroll
    for (int m = 0; m < 9; m++) { acc[m][0]=0.f; acc[m][1]=0.f; acc[m][2]=0.f; acc[m][3]=0.f; }

    unsigned as_base = (unsigned)__cvta_generic_to_shared(As);
    unsigned bs_base = (unsigned)__cvta_generic_to_shared(Bs);
    // A ldmatrix x4: lanes 0-15 -> rows 0-15 at col 0; lanes 16-31 -> rows 0-15 at col 8.
    unsigned a_lane_off = (unsigned)((((lane & 15) * APITCH) + ((lane >> 4) * 8)) * 2);
    // B ldmatrix x2 trans: lanes 0-15 -> k-rows 0-15 at this warp's n-tile.
    unsigned b_lane_addr = bs_base + (unsigned)((((lane & 15) * BPITCH) + warp * 8) * 2);

    const uint32_t* Bg32 = reinterpret_cast<const uint32_t*>(g_B);
    uint32_t* Bs32 = reinterpret_cast<uint32_t*>(Bs);

    for (int ch = 0; ch < NCHUNK; ch++) {
        __syncthreads();   // previous chunk's mma reads complete
        // stage B chunk: 16 rows x 32 u32 (coalesced from global)
        #pragma unroll
        for (int i = tid; i < 512; i += 256) {
            int r = i >> 5, jj = i & 31;
            Bs32[r * (BPITCH/2) + jj] = Bg32[(ch * 16 + r) * 32 + jj];
        }
        // build A chunk: 140 rows x 8 complex bins (k = ch*8 + bin)
        for (int i = tid; i < MROWS * 8; i += 256) {
            int rho = i >> 3, bin = i & 7;
            int k = ch * 8 + bin;
            __half2 val;
            if (k <= 512) {
                int p  = rho % NPAIRS;
                int tl = rho / NPAIRS;
                int t  = tblk * GT + tl;
                int base1 = ((b * NCH + c_i1[p]) * NT + t) * NBINS + k;
                int base2 = ((b * NCH + c_i2[p]) * NT + t) * NBINS + k;
                float2 a  = __half22float2(g_X[base1]);
                float2 cc = __half22float2(g_X[base2]);
                val = __floats2half2_rn(a.x*cc.x + a.y*cc.y, a.y*cc.x - a.x*cc.y);
            } else {
                val = __floats2half2_rn(0.0f, 0.0f);
            }
            *reinterpret_cast<__half2*>(&As[rho * APITCH + 2 * bin]) = val;
        }
        __syncthreads();

        unsigned b0, b1;
        asm volatile("ldmatrix.sync.aligned.m8n8.x2.trans.shared.b16 {%0,%1},[%2];"
                     : "=r"(b0), "=r"(b1) : "r"(b_lane_addr));
        #pragma unroll
        for (int mt = 0; mt < 9; mt++) {
            unsigned aaddr = as_base + (unsigned)(mt * 16 * APITCH * 2) + a_lane_off;
            unsigned a0, a1, a2, a3;
            asm volatile("ldmatrix.sync.aligned.m8n8.x4.shared.b16 {%0,%1,%2,%3},[%4];"
                         : "=r"(a0), "=r"(a1), "=r"(a2), "=r"(a3) : "r"(aaddr));
            asm volatile("mma.sync.aligned.m16n8k16.row.col.f32.f16.f16.f32 "
                         "{%0,%1,%2,%3},{%4,%5,%6,%7},{%8,%9},{%0,%1,%2,%3};"
                         : "+f"(acc[mt][0]), "+f"(acc[mt][1]), "+f"(acc[mt][2]), "+f"(acc[mt][3])
                         : "r"(a0), "r"(a1), "r"(a2), "r"(a3), "r"(b0), "r"(b1));
        }
    }

    // epilogue: D frag row = lane>>2 (+8), cols = (lane&3)*2, +1
    int row0 = lane >> 2;
    int col  = (lane & 3) * 2;
    #pragma unroll
    for (int mt = 0; mt < 9; mt++) {
        #pragma unroll
        for (int h = 0; h < 2; h++) {
            int rho = mt * 16 + row0 + h * 8;
            if (rho < MROWS) {
                int p  = rho % NPAIRS;
                int tl = rho / NPAIRS;
                int t  = tblk * GT + tl;
                float2 v = h ? make_float2(acc[mt][2], acc[mt][3])
                             : make_float2(acc[mt][0], acc[mt][1]);
                *reinterpret_cast<float2*>(
                    &out[((size_t)(b * NPAIRS + p) * NT + t) * NLAGS + warp * 8 + col]) = v;
            }
        }
    }
}

extern "C" void kernel_launch(void* const* d_in, const int* in_sizes, int n_in,
                              void* d_out, int out_size) {
    const float* x = (const float*)d_in[0];
    float* out = (float*)d_out;
    fwd_fft_kernel<<<NBATCH * NCH * NT, 64>>>(x);
    binit_kernel<<<(KKPAD * NLAGS + 255) / 256, 256>>>();
    xgemm_kernel<<<NBATCH * NTBLK, 256>>>(out);
}

// round 13
// speedup vs baseline: 1.2674x; 1.2674x over previous
#include <cuda_runtime.h>
#include <cuda_fp16.h>
#include <cstdint>

#define L_FFT   1024
#define NBINS   513
#define NBATCH  16
#define NCH     8
#define NT      250
#define NPAIRS  28
#define NLAGS   64
#define XPITCH  258   // uint2 slots per row (257 used; 16B-aligned pitch)

typedef unsigned long long ull;

// Scratch: PHASE-NORMALIZED spectra, paired-mirror layout.
// Slot k (k=0..255): {U[k], U[512-k]} as two fp16-complex; slot 0 = {U[0], U[512]};
// slot 256.x = U[256]. ~66 MB.
__device__ __align__(16) uint2 g_X[(size_t)NBATCH * NCH * NT * XPITCH];

__constant__ int c_i1[NPAIRS] = {0,0,0,0,0,0,0,1,1,1,1,1,1,2,2,2,2,2,3,3,3,3,4,4,4,5,5,6};
__constant__ int c_i2[NPAIRS] = {1,2,3,4,5,6,7,2,3,4,5,6,7,3,4,5,6,7,4,5,6,7,5,6,7,6,7,7};

// Pass-2 twiddle LUT: e^{2 pi i j / 64}, j = 0..7
__constant__ float2 c_w64[8] = {
    {1.0f, 0.0f},
    {0.99518472667219689f, 0.09801714032956060f},
    {0.98078528040323045f, 0.19509032201612827f},
    {0.95694033573220887f, 0.29028467725446234f},
    {0.92387953251128676f, 0.38268343236508977f},
    {0.88192126434835503f, 0.47139673682599764f},
    {0.83146961230254524f, 0.55557023301960222f},
    {0.77301045336273696f, 0.63439328416364549f}
};

union C64u { float2 f; ull u; };
__device__ __forceinline__ ull   F2U(float2 a){ C64u c; c.f=a; return c.u; }
__device__ __forceinline__ float2 U2F(ull a){ C64u c; c.u=a; return c.f; }

// Packed f32x2 ops (sm_100+): one instruction per complex add/sub.
__device__ __forceinline__ ull padd(ull a, ull b){ ull r; asm("add.rn.f32x2 %0,%1,%2;" : "=l"(r) : "l"(a), "l"(b)); return r; }
__device__ __forceinline__ ull psub(ull a, ull b){ ull r; asm("sub.rn.f32x2 %0,%1,%2;" : "=l"(r) : "l"(a), "l"(b)); return r; }
__device__ __forceinline__ ull pmulp(ull a, ull b){ ull r; asm("mul.rn.f32x2 %0,%1,%2;" : "=l"(r) : "l"(a), "l"(b)); return r; }

__device__ __forceinline__ float2 cadd(float2 a, float2 b){ return make_float2(a.x+b.x, a.y+b.y); }
__device__ __forceinline__ float2 cmul(float2 a, float2 b){ return make_float2(a.x*b.x - a.y*b.y, a.x*b.y + a.y*b.x); }

__device__ __forceinline__ float2 h2f(unsigned u){
    __half2 h = *reinterpret_cast<__half2*>(&u);
    return __half22float2(h);
}

// multiply by S*i  (S=+1: i, S=-1: -i)
template<int S>
__device__ __forceinline__ ull muli(ull a){
    float2 f = U2F(a);
    return F2U(S > 0 ? make_float2(-f.y, f.x) : make_float2(f.y, -f.x));
}

// Bank-conflict padding: one extra float2 every 8.
#define PD(i) ((i) + ((i) >> 3))
#define ABUF  576

// Natural-order radix-8 butterfly on packed complexes. S=-1 fwd, S=+1 inv.
template<int S>
__device__ __forceinline__ void pbfly8(ull v[8]) {
    const float Cc = 0.70710678118654752440f;
    const ull CC = F2U(make_float2(Cc, Cc));
    ull t0 = padd(v[0], v[4]), t4 = psub(v[0], v[4]);
    ull t1 = padd(v[1], v[5]), t5 = psub(v[1], v[5]);
    ull t2 = padd(v[2], v[6]), t6 = psub(v[2], v[6]);
    ull t3 = padd(v[3], v[7]), t7 = psub(v[3], v[7]);
    ull u5 = pmulp(CC, padd(t5, muli<S>(t5)));
    ull u6 = muli<S>(t6);
    ull u7 = pmulp(CC, psub(muli<S>(t7), t7));
    ull p0 = padd(t0, t2), q0 = psub(t0, t2);
    ull p1 = padd(t1, t3), q1 = muli<S>(psub(t1, t3));
    v[0] = padd(p0, p1); v[4] = psub(p0, p1);
    v[2] = padd(q0, q1); v[6] = psub(q0, q1);
    ull r0 = padd(t4, u6), s0 = psub(t4, u6);
    ull r1 = padd(u5, u7), s1 = muli<S>(psub(u5, u7));
    v[1] = padd(r0, r1); v[5] = psub(r0, r1);
    v[3] = padd(s0, s1); v[7] = psub(s0, s1);
}

// Inverse radix-8 butterfly producing ONLY outputs 0,1,6,7 (pass-2 prune).
__device__ __forceinline__ void pbfly8_0167(const ull v[8], ull& o0, ull& o1, ull& o6, ull& o7) {
    const float Cc = 0.70710678118654752440f;
    const ull CC = F2U(make_float2(Cc, Cc));
    ull t0 = padd(v[0], v[4]), t4 = psub(v[0], v[4]);
    ull t1 = padd(v[1], v[5]), t5 = psub(v[1], v[5]);
    ull t2 = padd(v[2], v[6]), t6 = psub(v[2], v[6]);
    ull t3 = padd(v[3], v[7]), t7 = psub(v[3], v[7]);
    ull u5 = pmulp(CC, padd(t5, muli<1>(t5)));
    ull u6 = muli<1>(t6);
    ull u7 = pmulp(CC, psub(muli<1>(t7), t7));
    ull p0 = padd(t0, t2), q0 = psub(t0, t2);
    ull p1 = padd(t1, t3), q1 = muli<1>(psub(t1, t3));
    o0 = padd(p0, p1);
    o6 = psub(q0, q1);
    ull r0 = padd(t4, u6), s0 = psub(t4, u6);
    ull r1 = padd(u5, u7), s1 = muli<1>(psub(u5, u7));
    o1 = padd(r0, r1);
    o7 = psub(s0, s1);
}

// v[j] *= w^j, j=1..7 (shallow power tree).
__device__ __forceinline__ void twiddle7(ull v[8], float2 w){
    float2 w2 = cmul(w,  w);
    float2 w3 = cmul(w2, w);
    float2 w4 = cmul(w2, w2);
    float2 w5 = cmul(w3, w2);
    float2 w6 = cmul(w3, w3);
    float2 w7 = cmul(w4, w3);
    v[1] = F2U(cmul(U2F(v[1]), w));
    v[2] = F2U(cmul(U2F(v[2]), w2));
    v[3] = F2U(cmul(U2F(v[3]), w3));
    v[4] = F2U(cmul(U2F(v[4]), w4));
    v[5] = F2U(cmul(U2F(v[5]), w5));
    v[6] = F2U(cmul(U2F(v[6]), w6));
    v[7] = F2U(cmul(U2F(v[7]), w7));
}

// Passes 2+3 of the 512-pt register FFT (full version, used by fwd kernel).
template<int S>
__device__ __forceinline__ void fft_mid(float2* A, ull v[8], int t){
    int n3 = t & 7;
    int b2 = 64 * (t >> 3) + n3;
    #pragma unroll
    for (int l = 0; l < 8; l++) v[l] = F2U(A[PD(b2 + 8*l)]);
    pbfly8<S>(v);
    {
        float2 w = c_w64[n3];
        twiddle7(v, S > 0 ? w : make_float2(w.x, -w.y));
    }
    #pragma unroll
    for (int l = 0; l < 8; l++) A[PD(b2 + 8*l)] = U2F(v[l]);
    __syncthreads();
    #pragma unroll
    for (int l = 0; l < 8; l++) v[l] = F2U(A[PD(8*t + l)]);
    pbfly8<S>(v);
}

// ---------------- Kernel A: forward rfft + PHAT phase-normalize ----------------
__global__ __launch_bounds__(64) void fwd_fft_kernel(const float* __restrict__ x) {
    __shared__ float2 A[ABUF];
    int t = threadIdx.x;
    int row = blockIdx.x;
    const float2* xin = reinterpret_cast<const float2*>(x + (size_t)row * L_FFT);

    float sT, cT; sincospif((float)t * (1.0f/512.0f), &sT, &cT);
    float2 Tt = make_float2(cT, sT);

    ull v[8];
    #pragma unroll
    for (int l = 0; l < 8; l++) v[l] = F2U(xin[t + 64*l]);
    pbfly8<-1>(v);
    {
        float2 T2 = cmul(Tt, Tt);
        twiddle7(v, make_float2(T2.x, -T2.y));
    }
    #pragma unroll
    for (int j = 0; j < 8; j++) A[PD(t + 64*j)] = U2F(v[j]);
    __syncthreads();

    fft_mid<-1>(A, v, t);
    __syncthreads();
    int base = (t >> 3) + 8 * (t & 7);
    #pragma unroll
    for (int m = 0; m < 8; m++) A[PD(base + 64*m)] = U2F(v[m]);
    __syncthreads();

    // Unpack + normalize; store unit phase into paired-mirror layout.
    unsigned* outp = reinterpret_cast<unsigned*>(g_X + (size_t)row * XPITCH);
    const float2 W64t = make_float2(0.92387953251128676f, 0.38268343236508977f);
    float sB, cB; sincospif((float)base * (1.0f/512.0f), &sB, &cB);
    float2 Tk = make_float2(cB, sB);
    #pragma unroll
    for (int m = 0; m < 8; m++) {
        int k = base + 64*m;
        float2 Zk = U2F(v[m]);
        float2 Zm = A[PD((512 - k) & 511)];
        float2 Ze = make_float2(0.5f * (Zk.x + Zm.x), 0.5f * (Zk.y - Zm.y));
        float2 D  = make_float2(Zk.x - Zm.x, Zk.y + Zm.y);
        float2 Zo = make_float2(0.5f * D.y, -0.5f * D.x);
        float2 tw = make_float2(Tk.x, -Tk.y);
        float2 X  = cadd(Ze, cmul(tw, Zo));
        float inv = rsqrtf(fmaxf(X.x*X.x + X.y*X.y, 1e-30f));
        __half2 h = __floats2half2_rn(X.x * inv, X.y * inv);
        int idx = (k <= 256) ? (2 * k) : (2 * (512 - k) + 1);
        outp[idx] = *reinterpret_cast<unsigned*>(&h);
        Tk = cmul(Tk, W64t);
    }
    if (t == 0) {   // bin 512 (real) -> slot 0, second word
        float2 Z0 = U2F(v[0]);
        float Xr = Z0.x - Z0.y;
        float inv = rsqrtf(fmaxf(Xr*Xr, 1e-30f));
        __half2 h = __floats2half2_rn(Xr * inv, 0.0f);
        outp[1] = *reinterpret_cast<unsigned*>(&h);
    }
}

// ------------- Kernel B: cross-phase + OUTPUT-PRUNED 64-lag inverse real FFT -------------
__global__ __launch_bounds__(64) void xcorr_kernel(float* __restrict__ out) {
    __shared__ float2 A[ABUF];
    int t = threadIdx.x;
    int id = blockIdx.x;                 // ((b*28 + p)*250 + tt)
    int tt = id % NT;
    int pr = (id / NT) % NPAIRS;
    int b  = id / (NT * NPAIRS);

    const uint2* X1 = g_X + (((size_t)(b * NCH + c_i1[pr])) * NT + tt) * XPITCH;
    const uint2* X2 = g_X + (((size_t)(b * NCH + c_i2[pr])) * NT + tt) * XPITCH;

    float sT, cT; sincospif((float)t * (1.0f/512.0f), &sT, &cT);
    float2 Tt = make_float2(cT, sT);
    const float2 W64t = make_float2(0.92387953251128676f, 0.38268343236508977f);

    // Partner-exchange Z-build. One LDG.64 per spectrum per bin-pair:
    // slot k = {U[k], U[512-k]}.
    ull v[8];
    float2 Tk = Tt;
    #pragma unroll
    for (int i = 0; i < 4; i++) {
        int k  = t + 64*i;          // k in [0,256)
        int km = 512 - k;
        uint2 u1 = X1[k];
        uint2 u2 = X2[k];
        float2 a1 = h2f(u1.x), a2 = h2f(u1.y);
        float2 c1 = h2f(u2.x), c2 = h2f(u2.y);
        float2 Ra = make_float2(a1.x*c1.x + a1.y*c1.y, a1.y*c1.x - a1.x*c1.y);
        float2 Rb = make_float2(a2.x*c2.x + a2.y*c2.y, a2.y*c2.x - a2.x*c2.y);
        // Z[k] from (Ra, Rb) with T_k  -> own register
        float2 Ze = make_float2(0.5f*(Ra.x + Rb.x), 0.5f*(Ra.y - Rb.y));
        float2 U  = make_float2(0.5f*(Ra.x - Rb.x), 0.5f*(Ra.y + Rb.y));
        float2 Zo = cmul(Tk, U);
        v[i] = F2U(make_float2(Ze.x - Zo.y, Ze.y + Zo.x));
        if (k > 0) {
            // Z[512-k] from (Rb, Ra) with T_{512-k} = (-Tk.x, Tk.y) -> partner
            float2 Ze2 = make_float2(0.5f*(Rb.x + Ra.x), 0.5f*(Rb.y - Ra.y));
            float2 U2  = make_float2(0.5f*(Rb.x - Ra.x), 0.5f*(Rb.y + Ra.y));
            float2 Zo2 = cmul(make_float2(-Tk.x, Tk.y), U2);
            A[PD(km)] = make_float2(Ze2.x - Zo2.y, Ze2.y + Zo2.x);
        }
        Tk = cmul(Tk, W64t);
    }
    if (t == 0) {   // slot 256: Z[256] = conj(R[256])
        float2 a = h2f(X1[256].x);
        float2 c = h2f(X2[256].x);
        A[PD(256)] = make_float2(a.x*c.x + a.y*c.y, -(a.y*c.x - a.x*c.y));
    }
    __syncthreads();
    #pragma unroll
    for (int i = 4; i < 8; i++) v[i] = F2U(A[PD(t + 64*i)]);

    // ---- pass 1 (full) ----
    pbfly8<1>(v);
    {
        float2 T2 = cmul(Tt, Tt);   // e^{+2pi i t/512}
        twiddle7(v, T2);
    }
    __syncthreads();   // partner loads complete before pass-1 stores overwrite
    #pragma unroll
    for (int j = 0; j < 8; j++) A[PD(t + 64*j)] = U2F(v[j]);
    __syncthreads();

    // ---- pass 2 (pruned butterfly: only outputs 0,1,6,7) ----
    ull z0, z1, z6, z7;
    {
        int n3 = t & 7;
        int b2 = 64 * (t >> 3) + n3;
        #pragma unroll
        for (int l = 0; l < 8; l++) v[l] = F2U(A[PD(b2 + 8*l)]);
        pbfly8_0167(v, z0, z1, z6, z7);
        float2 w  = c_w64[n3];            // e^{+2pi i n3/64}
        float2 w2 = cmul(w,  w);
        float2 w3 = cmul(w2, w);
        float2 w6 = cmul(w3, w3);
        float2 w7 = cmul(w6, w);
        z1 = F2U(cmul(U2F(z1), w));
        z6 = F2U(cmul(U2F(z6), w6));
        z7 = F2U(cmul(U2F(z7), w7));
    }
    __syncthreads();   // pass-2 reads done before pruned stores overwrite
    {
        int n3 = t & 7;
        int b2 = 64 * (t >> 3) + n3;
        A[PD(b2)]      = U2F(z0);
        A[PD(b2 + 8)]  = U2F(z1);
        A[PD(b2 + 48)] = U2F(z6);
        A[PD(b2 + 56)] = U2F(z7);
    }
    __syncthreads();

    // ---- pass 3 (pruned): thread t needs only output m=0 (r<2) or m=7 (r>5) ----
    int r = t & 7;
    if (r < 2 || r > 5) {
        // contiguous: PD(8t + l) = 9t + l
        ull in[8];
        #pragma unroll
        for (int l = 0; l < 8; l++) in[l] = F2U(A[9*t + l]);

        ull z;
        if (r < 2) {
            // m = 0: plain sum
            z = padd(padd(padd(in[0], in[1]), padd(in[2], in[3])),
                     padd(padd(in[4], in[5]), padd(in[6], in[7])));
        } else {
            // m = 7 (S=+1): sum_l in[l] * w8^{-l},  w8 = e^{+2pi i/8}
            const float Cc = 0.70710678118654752440f;
            const ull CC  = F2U(make_float2( Cc,  Cc));
            const ull CCn = F2U(make_float2(-Cc, -Cc));
            ull d0 = psub(in[0], in[4]);
            ull d1 = psub(in[1], in[5]);
            ull d2 = psub(in[2], in[6]);
            ull d3 = psub(in[3], in[7]);
            ull e1 = pmulp(CC,  padd(d1, muli<-1>(d1)));  // d1 * (C - Ci)
            ull e2 = muli<-1>(d2);                        // d2 * (-i)
            ull e3 = pmulp(CCn, padd(d3, muli< 1>(d3)));  // d3 * (-C - Ci)
            z = padd(padd(d0, e1), padd(e2, e3));
        }

        // n = (t>>3) + 8*r + 64*m ; x[2n]=Re z/512, x[2n+1]=Im z/512;
        // fftshift slice: n<16 -> orow[n+16], n>=496 -> orow[n-496].
        const float sc = 1.0f / 512.0f;
        float2 zz = U2F(z);
        float2* orow = reinterpret_cast<float2*>(out + (size_t)id * NLAGS);
        int q = t >> 3;
        if (r < 2) {
            int n = q + 8*r;            // in [0,16)
            orow[n + 16] = make_float2(zz.x * sc, zz.y * sc);
        } else {
            int n = 448 + q + 8*r;      // in [496,512)
            orow[n - 496] = make_float2(zz.x * sc, zz.y * sc);
        }
    }
}

extern "C" void kernel_launch(void* const* d_in, const int* in_sizes, int n_in,
                              void* d_out, int out_size) {
    const float* x = (const float*)d_in[0];
    float* out = (float*)d_out;
    fwd_fft_kernel<<<NBATCH * NCH * NT, 64>>>(x);
    xcorr_kernel<<<NBATCH * NPAIRS * NT, 64>>>(out);
}

// round 14
// speedup vs baseline: 1.9881x; 1.5687x over previous
#include <cuda_runtime.h>
#include <cuda_bf16.h>
#include <cuda_fp16.h>

#define L_FFT   1024
#define NBINS   513
#define NBATCH  16
#define NCH     8
#define NT      250
#define NPAIRS  28
#define NLAGS   64

typedef unsigned long long ull;

// Scratch: PHASE-NORMALIZED spectra (unit magnitude) in fp16 complex. ~66 MB.
__device__ __half2 g_X[(size_t)NBATCH * NCH * NT * NBINS];

__constant__ int c_i1[NPAIRS] = {0,0,0,0,0,0,0,1,1,1,1,1,1,2,2,2,2,2,3,3,3,3,4,4,4,5,5,6};
__constant__ int c_i2[NPAIRS] = {1,2,3,4,5,6,7,2,3,4,5,6,7,3,4,5,6,7,4,5,6,7,5,6,7,6,7,7};

// Pass-2 twiddle LUT: e^{2 pi i j / 64}, j = 0..7
__constant__ float2 c_w64[8] = {
    {1.0f, 0.0f},
    {0.99518472667219689f, 0.09801714032956060f},
    {0.98078528040323045f, 0.19509032201612827f},
    {0.95694033573220887f, 0.29028467725446234f},
    {0.92387953251128676f, 0.38268343236508977f},
    {0.88192126434835503f, 0.47139673682599764f},
    {0.83146961230254524f, 0.55557023301960222f},
    {0.77301045336273696f, 0.63439328416364549f}
};

union C64u { float2 f; ull u; };
__device__ __forceinline__ ull   F2U(float2 a){ C64u c; c.f=a; return c.u; }
__device__ __forceinline__ float2 U2F(ull a){ C64u c; c.u=a; return c.f; }

// Packed f32x2 ops (sm_100+): one instruction per complex add/sub.
__device__ __forceinline__ ull padd(ull a, ull b){ ull r; asm("add.rn.f32x2 %0,%1,%2;" : "=l"(r) : "l"(a), "l"(b)); return r; }
__device__ __forceinline__ ull psub(ull a, ull b){ ull r; asm("sub.rn.f32x2 %0,%1,%2;" : "=l"(r) : "l"(a), "l"(b)); return r; }
__device__ __forceinline__ ull pmulp(ull a, ull b){ ull r; asm("mul.rn.f32x2 %0,%1,%2;" : "=l"(r) : "l"(a), "l"(b)); return r; }

__device__ __forceinline__ float2 cadd(float2 a, float2 b){ return make_float2(a.x+b.x, a.y+b.y); }
__device__ __forceinline__ float2 cmul(float2 a, float2 b){ return make_float2(a.x*b.x - a.y*b.y, a.x*b.y + a.y*b.x); }

// multiply by S*i  (S=+1: i, S=-1: -i)
template<int S>
__device__ __forceinline__ ull muli(ull a){
    float2 f = U2F(a);
    return F2U(S > 0 ? make_float2(-f.y, f.x) : make_float2(f.y, -f.x));
}

// Bank-conflict padding: one extra float2 every 8.
#define PD(i) ((i) + ((i) >> 3))
#define ABUF  576

// Natural-order radix-8 butterfly on packed complexes. S=-1 fwd, S=+1 inv.
template<int S>
__device__ __forceinline__ void pbfly8(ull v[8]) {
    const float Cc = 0.70710678118654752440f;
    const ull CC = F2U(make_float2(Cc, Cc));
    ull t0 = padd(v[0], v[4]), t4 = psub(v[0], v[4]);
    ull t1 = padd(v[1], v[5]), t5 = psub(v[1], v[5]);
    ull t2 = padd(v[2], v[6]), t6 = psub(v[2], v[6]);
    ull t3 = padd(v[3], v[7]), t7 = psub(v[3], v[7]);
    ull u5 = pmulp(CC, padd(t5, muli<S>(t5)));
    ull u6 = muli<S>(t6);
    ull u7 = pmulp(CC, psub(muli<S>(t7), t7));
    ull p0 = padd(t0, t2), q0 = psub(t0, t2);
    ull p1 = padd(t1, t3), q1 = muli<S>(psub(t1, t3));
    v[0] = padd(p0, p1); v[4] = psub(p0, p1);
    v[2] = padd(q0, q1); v[6] = psub(q0, q1);
    ull r0 = padd(t4, u6), s0 = psub(t4, u6);
    ull r1 = padd(u5, u7), s1 = muli<S>(psub(u5, u7));
    v[1] = padd(r0, r1); v[5] = psub(r0, r1);
    v[3] = padd(s0, s1); v[7] = psub(s0, s1);
}

// Inverse radix-8 butterfly producing ONLY outputs 0,1,6,7 (pass-2 prune).
__device__ __forceinline__ void pbfly8_0167(const ull v[8], ull& o0, ull& o1, ull& o6, ull& o7) {
    const float Cc = 0.70710678118654752440f;
    const ull CC = F2U(make_float2(Cc, Cc));
    ull t0 = padd(v[0], v[4]), t4 = psub(v[0], v[4]);
    ull t1 = padd(v[1], v[5]), t5 = psub(v[1], v[5]);
    ull t2 = padd(v[2], v[6]), t6 = psub(v[2], v[6]);
    ull t3 = padd(v[3], v[7]), t7 = psub(v[3], v[7]);
    ull u5 = pmulp(CC, padd(t5, muli<1>(t5)));
    ull u6 = muli<1>(t6);
    ull u7 = pmulp(CC, psub(muli<1>(t7), t7));
    ull p0 = padd(t0, t2), q0 = psub(t0, t2);
    ull p1 = padd(t1, t3), q1 = muli<1>(psub(t1, t3));
    o0 = padd(p0, p1);
    o6 = psub(q0, q1);
    ull r0 = padd(t4, u6), s0 = psub(t4, u6);
    ull r1 = padd(u5, u7), s1 = muli<1>(psub(u5, u7));
    o1 = padd(r0, r1);
    o7 = psub(s0, s1);
}

// v[j] *= w^j, j=1..7 (shallow power tree).
__device__ __forceinline__ void twiddle7(ull v[8], float2 w){
    float2 w2 = cmul(w,  w);
    float2 w3 = cmul(w2, w);
    float2 w4 = cmul(w2, w2);
    float2 w5 = cmul(w3, w2);
    float2 w6 = cmul(w3, w3);
    float2 w7 = cmul(w4, w3);
    v[1] = F2U(cmul(U2F(v[1]), w));
    v[2] = F2U(cmul(U2F(v[2]), w2));
    v[3] = F2U(cmul(U2F(v[3]), w3));
    v[4] = F2U(cmul(U2F(v[4]), w4));
    v[5] = F2U(cmul(U2F(v[5]), w5));
    v[6] = F2U(cmul(U2F(v[6]), w6));
    v[7] = F2U(cmul(U2F(v[7]), w7));
}

// Passes 2+3 of the 512-pt register FFT (full version, used by fwd kernel).
template<int S>
__device__ __forceinline__ void fft_mid(float2* A, ull v[8], int t){
    int n3 = t & 7;
    int b2 = 64 * (t >> 3) + n3;
    #pragma unroll
    for (int l = 0; l < 8; l++) v[l] = F2U(A[PD(b2 + 8*l)]);
    pbfly8<S>(v);
    {
        float2 w = c_w64[n3];
        twiddle7(v, S > 0 ? w : make_float2(w.x, -w.y));
    }
    #pragma unroll
    for (int l = 0; l < 8; l++) A[PD(b2 + 8*l)] = U2F(v[l]);
    __syncthreads();
    #pragma unroll
    for (int l = 0; l < 8; l++) v[l] = F2U(A[PD(8*t + l)]);
    pbfly8<S>(v);
}

// ---------------- Kernel A: forward rfft + PHAT phase-normalize ----------------
__global__ __launch_bounds__(64) void fwd_fft_kernel(const float* __restrict__ x) {
    __shared__ float2 A[ABUF];
    int t = threadIdx.x;
    int row = blockIdx.x;
    const float2* xin = reinterpret_cast<const float2*>(x + (size_t)row * L_FFT);

    float sT, cT; sincospif((float)t * (1.0f/512.0f), &sT, &cT);  // T_t = e^{2pi i t/1024}
    float2 Tt = make_float2(cT, sT);

    ull v[8];
    #pragma unroll
    for (int l = 0; l < 8; l++) v[l] = F2U(xin[t + 64*l]);
    pbfly8<-1>(v);
    {
        float2 T2 = cmul(Tt, Tt);                  // e^{2pi i t/512}
        twiddle7(v, make_float2(T2.x, -T2.y));     // conj for forward
    }
    #pragma unroll
    for (int j = 0; j < 8; j++) A[PD(t + 64*j)] = U2F(v[j]);
    __syncthreads();

    fft_mid<-1>(A, v, t);
    __syncthreads();   // all pass-3 reads done before scatter overwrites
    // scatter Z to natural order (needed only for cross-thread mirror reads)
    int base = (t >> 3) + 8 * (t & 7);
    #pragma unroll
    for (int m = 0; m < 8; m++) A[PD(base + 64*m)] = U2F(v[m]);
    __syncthreads();

    // Unpack + normalize; store unit-magnitude phase as fp16 complex.
    __half2* outp = g_X + (size_t)row * NBINS;
    const float2 W64t = make_float2(0.92387953251128676f, 0.38268343236508977f); // e^{i pi/8}
    float sB, cB; sincospif((float)base * (1.0f/512.0f), &sB, &cB);
    float2 Tk = make_float2(cB, sB);               // e^{2pi i base/1024}
    #pragma unroll
    for (int m = 0; m < 8; m++) {
        int k = base + 64*m;
        float2 Zk = U2F(v[m]);
        float2 Zm = A[PD((512 - k) & 511)];
        float2 Ze = make_float2(0.5f * (Zk.x + Zm.x), 0.5f * (Zk.y - Zm.y));
        float2 D  = make_float2(Zk.x - Zm.x, Zk.y + Zm.y);
        float2 Zo = make_float2(0.5f * D.y, -0.5f * D.x);
        float2 tw = make_float2(Tk.x, -Tk.y);
        float2 X  = cadd(Ze, cmul(tw, Zo));
        float inv = rsqrtf(fmaxf(X.x*X.x + X.y*X.y, 1e-30f));
        outp[k] = __floats2half2_rn(X.x * inv, X.y * inv);
        Tk = cmul(Tk, W64t);
    }
    if (t == 0) {   // base == 0: bin 512 is X = Z0.x - Z0.y (real), Z0 = v[0]
        float2 Z0 = U2F(v[0]);
        float Xr = Z0.x - Z0.y;
        float inv = rsqrtf(fmaxf(Xr*Xr, 1e-30f));
        outp[512] = __floats2half2_rn(Xr * inv, 0.0f);
    }
}

// ------------- Kernel B: cross-phase + OUTPUT-PRUNED 64-lag inverse real FFT -------------
__global__ __launch_bounds__(64) void xcorr_kernel(float* __restrict__ out) {
    __shared__ float2 A[ABUF];
    int t = threadIdx.x;
    int id = blockIdx.x;                 // ((b*28 + p)*250 + tt)
    int tt = id % NT;
    int pr = (id / NT) % NPAIRS;
    int b  = id / (NT * NPAIRS);

    const __half2* X1 = g_X + (((size_t)(b * NCH + c_i1[pr])) * NT + tt) * NBINS;
    const __half2* X2 = g_X + (((size_t)(b * NCH + c_i2[pr])) * NT + tt) * NBINS;

    float sT, cT; sincospif((float)t * (1.0f/512.0f), &sT, &cT);
    float2 Tt = make_float2(cT, sT);
    const float2 W64t = make_float2(0.92387953251128676f, 0.38268343236508977f);

    // Partner-exchange Z-build: thread t's pass-1 slots are k = t+64i.
    // It computes Z[k] for i=0..3 itself (keeps in regs v[0..3]); the mirror
    // Z[512-k] belongs to thread 64-t (regs 7-i) and goes through shared.
    ull v[8];
    float2 Tk = Tt;
    #pragma unroll
    for (int i = 0; i < 4; i++) {
        int k  = t + 64*i;          // k in [0,256)
        int km = 512 - k;
        float2 a1 = __half22float2(X1[k]);
        float2 c1 = __half22float2(X2[k]);
        float2 a2 = __half22float2(X1[km]);
        float2 c2 = __half22float2(X2[km]);
        float2 Ra = make_float2(a1.x*c1.x + a1.y*c1.y, a1.y*c1.x - a1.x*c1.y);
        float2 Rb = make_float2(a2.x*c2.x + a2.y*c2.y, a2.y*c2.x - a2.x*c2.y);
        // Z[k] from (Ra, Rb) with T_k  -> own register
        float2 Ze = make_float2(0.5f*(Ra.x + Rb.x), 0.5f*(Ra.y - Rb.y));
        float2 U  = make_float2(0.5f*(Ra.x - Rb.x), 0.5f*(Ra.y + Rb.y));
        float2 Zo = cmul(Tk, U);
        v[i] = F2U(make_float2(Ze.x - Zo.y, Ze.y + Zo.x));
        if (k > 0) {
            // Z[512-k] from (Rb, Ra) with T_{512-k} = (-Tk.x, Tk.y) -> partner
            float2 Ze2 = make_float2(0.5f*(Rb.x + Ra.x), 0.5f*(Rb.y - Ra.y));
            float2 U2  = make_float2(0.5f*(Rb.x - Ra.x), 0.5f*(Rb.y + Ra.y));
            float2 Zo2 = cmul(make_float2(-Tk.x, Tk.y), U2);
            A[PD(km)] = make_float2(Ze2.x - Zo2.y, Ze2.y + Zo2.x);
        }
        Tk = cmul(Tk, W64t);
    }
    if (t == 0) {   // slot 256: Z[256] = conj(R[256])
        float2 a = __half22float2(X1[256]);
        float2 c = __half22float2(X2[256]);
        A[PD(256)] = make_float2(a.x*c.x + a.y*c.y, -(a.y*c.x - a.x*c.y));
    }
    __syncthreads();
    #pragma unroll
    for (int i = 4; i < 8; i++) v[i] = F2U(A[PD(t + 64*i)]);

    // ---- pass 1 (full) ----
    pbfly8<1>(v);
    {
        float2 T2 = cmul(Tt, Tt);   // e^{+2pi i t/512}
        twiddle7(v, T2);
    }
    __syncthreads();   // partner loads complete before pass-1 stores overwrite
    #pragma unroll
    for (int j = 0; j < 8; j++) A[PD(t + 64*j)] = U2F(v[j]);
    __syncthreads();

    // ---- pass 2 (pruned butterfly: only outputs 0,1,6,7 computed & stored) ----
    ull z0, z1, z6, z7;
    {
        int n3 = t & 7;
        int b2 = 64 * (t >> 3) + n3;
        #pragma unroll
        for (int l = 0; l < 8; l++) v[l] = F2U(A[PD(b2 + 8*l)]);
        pbfly8_0167(v, z0, z1, z6, z7);
        float2 w  = c_w64[n3];            // e^{+2pi i n3/64}
        float2 w2 = cmul(w,  w);
        float2 w3 = cmul(w2, w);
        float2 w6 = cmul(w3, w3);
        float2 w7 = cmul(w6, w);
        z1 = F2U(cmul(U2F(z1), w));
        z6 = F2U(cmul(U2F(z6), w6));
        z7 = F2U(cmul(U2F(z7), w7));
    }
    __syncthreads();   // pass-2 reads done before pruned stores overwrite
    {
        int n3 = t & 7;
        int b2 = 64 * (t >> 3) + n3;
        A[PD(b2)]      = U2F(z0);
        A[PD(b2 + 8)]  = U2F(z1);
        A[PD(b2 + 48)] = U2F(z6);
        A[PD(b2 + 56)] = U2F(z7);
    }
    __syncthreads();

    // ---- pass 3 (pruned): thread t needs only output m=0 (r<2) or m=7 (r>5) ----
    int r = t & 7;
    if (r < 2 || r > 5) {
        // contiguous: PD(8t + l) = 9t + l
        ull in[8];
        #pragma unroll
        for (int l = 0; l < 8; l++) in[l] = F2U(A[9*t + l]);

        ull z;
        if (r < 2) {
            // m = 0: plain sum
            z = padd(padd(padd(in[0], in[1]), padd(in[2], in[3])),
                     padd(padd(in[4], in[5]), padd(in[6], in[7])));
        } else {
            // m = 7 (S=+1): sum_l in[l] * w8^{-l},  w8 = e^{+2pi i/8}
            const float Cc = 0.70710678118654752440f;
            const ull CC  = F2U(make_float2( Cc,  Cc));
            const ull CCn = F2U(make_float2(-Cc, -Cc));
            ull d0 = psub(in[0], in[4]);
            ull d1 = psub(in[1], in[5]);
            ull d2 = psub(in[2], in[6]);
            ull d3 = psub(in[3], in[7]);
            ull e1 = pmulp(CC,  padd(d1, muli<-1>(d1)));  // d1 * (C - Ci)
            ull e2 = muli<-1>(d2);                        // d2 * (-i)
            ull e3 = pmulp(CCn, padd(d3, muli< 1>(d3)));  // d3 * (-C - Ci)
            z = padd(padd(d0, e1), padd(e2, e3));
        }

        // n = (t>>3) + 8*r + 64*m ; x[2n]=Re z/512, x[2n+1]=Im z/512;
        // fftshift slice: n<16 -> orow[n+16], n>=496 -> orow[n-496].
        const float sc = 1.0f / 512.0f;
        float2 zz = U2F(z);
        float2* orow = reinterpret_cast<float2*>(out + (size_t)id * NLAGS);
        int q = t >> 3;
        if (r < 2) {
            int n = q + 8*r;            // in [0,16)
            orow[n + 16] = make_float2(zz.x * sc, zz.y * sc);
        } else {
            int n = 448 + q + 8*r;      // in [496,512)
            orow[n - 496] = make_float2(zz.x * sc, zz.y * sc);
        }
    }
}

extern "C" void kernel_launch(void* const* d_in, const int* in_sizes, int n_in,
                              void* d_out, int out_size) {
    const float* x = (const float*)d_in[0];
    float* out = (float*)d_out;
    fwd_fft_kernel<<<NBATCH * NCH * NT, 64>>>(x);
    xcorr_kernel<<<NBATCH * NPAIRS * NT, 64>>>(out);
}